// round 12
// baseline (speedup 1.0000x reference)
#include <cuda_runtime.h>
#include <cuda_fp16.h>
#include <cstdint>

#define B_ 8192
#define C_ 64
#define K_ 256
#define D_ 64
#define BTILE 64
#define NTILES 8192
#define NBLK 296
#define MARGIN 4e-3f

// ---------------- scratch (static __device__) ----------------
__device__ float g_val[B_ * C_];
__device__ int   g_idx[B_ * C_];
__device__ float g_sum[C_];
__device__ float g_sumsq[C_];
__device__ unsigned char g_flag[B_ * C_];

__device__ __forceinline__ unsigned fkey(float f) {
    unsigned u = __float_as_uint(f);
    return (u & 0x80000000u) ? ~u : (u | 0x80000000u);
}
__device__ __forceinline__ float fkey_inv(unsigned key) {
    unsigned u = (key & 0x80000000u) ? (key ^ 0x80000000u) : ~key;
    return __uint_as_float(u);
}
__device__ __forceinline__ uint32_t smem_u32(const void* p) {
    uint32_t a;
    asm("{ .reg .u64 t; cvta.to.shared.u64 t, %1; cvt.u32.u64 %0, t; }" : "=r"(a) : "l"(p));
    return a;
}

#define LDSM_X4(r0, r1, r2, r3, addr) \
    asm volatile("ldmatrix.sync.aligned.m8n8.x4.shared.b16 {%0,%1,%2,%3}, [%4];" \
        : "=r"(r0), "=r"(r1), "=r"(r2), "=r"(r3) : "r"(addr))
#define MMA_F16(c, a, b0, b1) \
    asm volatile("mma.sync.aligned.m16n8k16.row.col.f32.f16.f16.f32 " \
        "{%0,%1,%2,%3}, {%4,%5,%6,%7}, {%8,%9}, {%0,%1,%2,%3};" \
        : "+f"((c)[0]), "+f"((c)[1]), "+f"((c)[2]), "+f"((c)[3]) \
        : "r"((a)[0]), "r"((a)[1]), "r"((a)[2]), "r"((a)[3]), "r"(b0), "r"(b1))

// ---------------- smem layout (bytes) ----------------
#define SM_REDQ1 0                       // u64[2][64]
#define SM_REDQ2 1024                    // u64[2][64]
#define SM_WSUM  2048                    // f32[16]
#define SM_A     4096                    // 8192 (64x64 fp16)
#define SM_B     (4096 + 8192)           // 32768 (256x64 fp16)
#define SM_TOTAL (4096 + 8192 + 32768)   // 45056

__global__ void init_kernel() {
    int t = threadIdx.x;
    if (t < C_) { g_sum[t] = 0.f; g_sumsq[t] = 0.f; }
}

__device__ __forceinline__ uint32_t sw_off(int row, int cbyte) {
    return (uint32_t)(row * 128 + (cbyte ^ ((row & 7) << 4)));
}

// merge two (top1, top2) sets, each with q1 >= q2
__device__ __forceinline__ void top2_merge(unsigned long long& q1, unsigned long long& q2,
                                           unsigned long long o1, unsigned long long o2) {
    unsigned long long n1 = (q1 > o1) ? q1 : o1;
    unsigned long long lo = (q1 > o1) ? o1 : q1;
    unsigned long long hi2 = (q2 > o2) ? q2 : o2;
    q1 = n1;
    q2 = (lo > hi2) ? lo : hi2;
}

__global__ void __launch_bounds__(256, 2)
score_kernel(const float* __restrict__ inp, const float* __restrict__ cent,
             const float* __restrict__ gamma) {
    extern __shared__ char smem[];
    const int tid  = threadIdx.x;
    const int lane = tid & 31;
    const int wid  = tid >> 5;
    const int warpM = wid & 3;        // rows 16*warpM .. +15
    const int warpN = wid >> 2;       // cols 128*warpN .. +127

    const uint32_t smem_base = smem_u32(smem);
    const uint32_t sA = smem_base + SM_A;
    const uint32_t sB = smem_base + SM_B;

    const int arow = warpM * 16 + (lane & 15);
    const uint32_t aoff0 = (uint32_t)(arow * 128);
    const uint32_t aswz = (uint32_t)((arow & 7) << 4);
    const int brow = warpN * 128 + (lane & 15);
    const uint32_t boff0 = (uint32_t)(brow * 128);
    const uint32_t bswz = (uint32_t)((brow & 7) << 4);
    const uint32_t lane16 = (uint32_t)(lane & 16);

    const int T0 = (blockIdx.x * NTILES) / NBLK;
    const int T1 = ((blockIdx.x + 1) * NTILES) / NBLK;

    int cur_c = -1;
    bool useMax = true;

    for (int T = T0; T < T1; T++) {
        const int c  = T >> 7;
        const int b0 = (T & 127) * BTILE;

        // ---- (re)fill B on channel change: fp16 hi part only ----
        if (c != cur_c) {
            __syncthreads();
            cur_c = c;
            useMax = (gamma[c] >= 0.f);
            const float* Bb = cent + (size_t)c * (K_ * D_);
            for (int t = tid; t < K_ * 16; t += 256) {
                int r = t >> 4;
                int d = (t & 15) << 2;
                float4 v = *(const float4*)(Bb + (size_t)r * D_ + d);
                uint16_t h0 = __half_as_ushort(__float2half_rn(v.x));
                uint16_t h1 = __half_as_ushort(__float2half_rn(v.y));
                uint16_t h2 = __half_as_ushort(__float2half_rn(v.z));
                uint16_t h3 = __half_as_ushort(__float2half_rn(v.w));
                *(uint64_t*)(smem + SM_B + sw_off(r, d * 2)) =
                    (uint64_t)h0 | ((uint64_t)h1 << 16) | ((uint64_t)h2 << 32) | ((uint64_t)h3 << 48);
            }
        }

        // ---- fill A tile (64 rows, fp16 hi only) ----
        {
            const float* Ab = inp + (size_t)b0 * (C_ * D_) + (size_t)c * D_;
            for (int t = tid; t < BTILE * 16; t += 256) {
                int r = t >> 4;
                int d = (t & 15) << 2;
                float4 v = *(const float4*)(Ab + (size_t)r * (C_ * D_) + d);
                uint16_t h0 = __half_as_ushort(__float2half_rn(v.x));
                uint16_t h1 = __half_as_ushort(__float2half_rn(v.y));
                uint16_t h2 = __half_as_ushort(__float2half_rn(v.z));
                uint16_t h3 = __half_as_ushort(__float2half_rn(v.w));
                *(uint64_t*)(smem + SM_A + sw_off(r, d * 2)) =
                    (uint64_t)h0 | ((uint64_t)h1 << 16) | ((uint64_t)h2 << 32) | ((uint64_t)h3 << 48);
            }
        }
        __syncthreads();

        // ---- preload A fragments ----
        uint32_t ah[4][4];
        uint32_t bko[4];
#pragma unroll
        for (int ks = 0; ks < 4; ks++) {
            uint32_t kcb = (uint32_t)(ks * 32) + lane16;
            uint32_t addr = sA + aoff0 + (kcb ^ aswz);
            LDSM_X4(ah[ks][0], ah[ks][1], ah[ks][2], ah[ks][3], addr);
            bko[ks] = kcb ^ bswz;
        }
        const uint32_t bbase = sB + boff0;

        // ---- single hh MMA pass ----
        float acc[16][4];
#pragma unroll
        for (int j = 0; j < 16; j++)
#pragma unroll
            for (int e = 0; e < 4; e++) acc[j][e] = 0.f;

#pragma unroll
        for (int ks = 0; ks < 4; ks++) {
#pragma unroll
            for (int p = 0; p < 8; p++) {
                uint32_t b0r, b1r, b2r, b3r;
                LDSM_X4(b0r, b1r, b2r, b3r, bbase + (uint32_t)(p * 2048) + bko[ks]);
                MMA_F16(acc[2 * p],     ah[ks], b0r, b2r);
                MMA_F16(acc[2 * p + 1], ah[ks], b1r, b3r);
            }
        }

        // ---- epilogue: top-2 per row + sums ----
        unsigned long long q1[2] = {0ull, 0ull}, q2[2] = {0ull, 0ull};
        float s = 0.f, s2 = 0.f;
#pragma unroll
        for (int j = 0; j < 16; j++) {
#pragma unroll
            for (int e = 0; e < 4; e++) {
                float v = acc[j][e];
                s += v;
                s2 = fmaf(v, v, s2);
                int k = warpN * 128 + j * 8 + 2 * (lane & 3) + (e & 1);
                unsigned key = fkey(v);
                if (!useMax) key = ~key;
                unsigned long long p = ((unsigned long long)key << 32) | (unsigned)(255 - k);
                int r = (e >> 1);
                if (p > q1[r]) { q2[r] = q1[r]; q1[r] = p; }
                else if (p > q2[r]) q2[r] = p;
            }
        }
#pragma unroll
        for (int sh = 1; sh <= 2; sh <<= 1) {
#pragma unroll
            for (int r = 0; r < 2; r++) {
                unsigned long long o1 = __shfl_xor_sync(0xffffffffu, q1[r], sh);
                unsigned long long o2 = __shfl_xor_sync(0xffffffffu, q2[r], sh);
                top2_merge(q1[r], q2[r], o1, o2);
            }
        }
        unsigned long long* rq1 = (unsigned long long*)(smem + SM_REDQ1);  // [2][64]
        unsigned long long* rq2 = (unsigned long long*)(smem + SM_REDQ2);
        if ((lane & 3) == 0) {
            int rl = warpM * 16 + (lane >> 2);
            rq1[warpN * 64 + rl] = q1[0];
            rq2[warpN * 64 + rl] = q2[0];
            rq1[warpN * 64 + rl + 8] = q1[1];
            rq2[warpN * 64 + rl + 8] = q2[1];
        }
#pragma unroll
        for (int sh = 16; sh > 0; sh >>= 1) {
            s  += __shfl_xor_sync(0xffffffffu, s,  sh);
            s2 += __shfl_xor_sync(0xffffffffu, s2, sh);
        }
        float* wsum = (float*)(smem + SM_WSUM);
        if (lane == 0) { wsum[wid] = s; wsum[8 + wid] = s2; }
        __syncthreads();

        if (tid < BTILE) {
            unsigned long long a1 = rq1[tid], a2 = rq2[tid];
            unsigned long long b1 = rq1[64 + tid], b2 = rq2[64 + tid];
            top2_merge(a1, a2, b1, b2);
            unsigned key1 = (unsigned)(a1 >> 32);
            unsigned key2 = (unsigned)(a2 >> 32);
            float v1 = fkey_inv(useMax ? key1 : ~key1);
            float v2 = fkey_inv(useMax ? key2 : ~key2);
            int rowid = (b0 + tid) * C_ + c;
            g_val[rowid] = v1;
            g_idx[rowid] = 255 - (int)(a1 & 0xFFu);
            g_flag[rowid] = (fabsf(v1 - v2) < MARGIN) ? 1 : 0;
        }
        if (tid == 0) {
            float t1 = 0.f, t2 = 0.f;
#pragma unroll
            for (int w = 0; w < 8; w++) { t1 += wsum[w]; t2 += wsum[8 + w]; }
            atomicAdd(&g_sum[c], t1);
            atomicAdd(&g_sumsq[c], t2);
        }
        __syncthreads();
    }
}

// ---------------- exact fp32 rescore of flagged rows (ballot scan) ----------------
__global__ void __launch_bounds__(256, 2)
rescore_kernel(const float* __restrict__ inp, const float* __restrict__ cent,
               const float* __restrict__ gamma) {
    const int lane = threadIdx.x & 31;
    const int gw = (blockIdx.x * 256 + threadIdx.x) >> 5;   // global warp id
    const int nw = gridDim.x * 8;

    for (int base = gw * 32; base < B_ * C_; base += nw * 32) {
        unsigned f = (unsigned)g_flag[base + lane];
        unsigned mask = __ballot_sync(0xffffffffu, f != 0u);
        while (mask) {
            int bit = __ffs(mask) - 1;
            mask &= mask - 1;
            int rowid = base + bit;
            int c = rowid & (C_ - 1);
            int b = rowid >> 6;
            bool useMax = (gamma[c] >= 0.f);

            const float4* x4 = (const float4*)(inp + (size_t)b * (C_ * D_) + (size_t)c * D_);
            float4 xr[16];
#pragma unroll
            for (int d = 0; d < 16; d++) xr[d] = __ldg(&x4[d]);

            unsigned long long best = 0ull;
#pragma unroll 1
            for (int j = 0; j < 8; j++) {
                int k = j * 32 + lane;
                const float4* y4 = (const float4*)(cent + (size_t)c * (K_ * D_) + (size_t)k * D_);
                float dot = 0.f;
#pragma unroll
                for (int d = 0; d < 16; d++) {
                    float4 y = __ldg(&y4[d]);
                    dot = fmaf(xr[d].x, y.x, dot);
                    dot = fmaf(xr[d].y, y.y, dot);
                    dot = fmaf(xr[d].z, y.z, dot);
                    dot = fmaf(xr[d].w, y.w, dot);
                }
                unsigned key = fkey(dot);
                if (!useMax) key = ~key;
                unsigned long long p = ((unsigned long long)key << 32) | (unsigned)(255 - k);
                best = (p > best) ? p : best;
            }
#pragma unroll
            for (int sh = 16; sh > 0; sh >>= 1) {
                unsigned long long o = __shfl_xor_sync(0xffffffffu, best, sh);
                best = (o > best) ? o : best;
            }
            if (lane == 0) {
                unsigned key = (unsigned)(best >> 32);
                g_val[rowid] = fkey_inv(useMax ? key : ~key);
                g_idx[rowid] = 255 - (int)(best & 0xFFu);
            }
            __syncwarp();
        }
    }
}

// ---------------- finalize: BN affine + emit ----------------
__global__ void finalize_kernel(const float* __restrict__ gamma,
                                const float* __restrict__ beta,
                                float* __restrict__ out_codes,
                                float* __restrict__ out_mse) {
    int tid = blockIdx.x * 256 + threadIdx.x;
    if (tid >= B_ * C_) return;
    int c = tid & (C_ - 1);
    const float Ninv = 1.f / ((float)B_ * (float)K_);
    float mean = g_sum[c] * Ninv;
    float var  = fmaf(-mean, mean, g_sumsq[c] * Ninv);
    float scale = gamma[c] * rsqrtf(var + 1e-5f);
    float shift = fmaf(-mean, scale, beta[c]);
    out_codes[tid] = (float)g_idx[tid];
    out_mse[tid]   = fmaf(g_val[tid], scale, shift);
}

__global__ void copy_kernel(const float4* __restrict__ src,
                            float4* __restrict__ dst, int n4) {
    int i = blockIdx.x * blockDim.x + threadIdx.x;
    if (i < n4) dst[i] = src[i];
}

extern "C" void kernel_launch(void* const* d_in, const int* in_sizes, int n_in,
                              void* d_out, int out_size) {
    const float* inp   = (const float*)d_in[0];
    const float* cent  = (const float*)d_in[1];
    const float* gamma = (const float*)d_in[2];
    const float* beta  = (const float*)d_in[3];
    float* out = (float*)d_out;

    cudaFuncSetAttribute(score_kernel,
                         cudaFuncAttributeMaxDynamicSharedMemorySize, SM_TOTAL);

    init_kernel<<<1, 64>>>();

    score_kernel<<<NBLK, 256, SM_TOTAL>>>(inp, cent, gamma);

    rescore_kernel<<<128, 256>>>(inp, cent, gamma);

    finalize_kernel<<<(B_ * C_ + 255) / 256, 256>>>(gamma, beta,
                                                    out, out + B_ * C_);

    if (out_size >= 2 * B_ * C_ + C_ * K_ * D_) {
        int n4 = (C_ * K_ * D_) / 4;
        copy_kernel<<<(n4 + 255) / 256, 256>>>((const float4*)cent,
                                               (float4*)(out + 2 * B_ * C_), n4);
    }
}

// round 14
// speedup vs baseline: 1.4681x; 1.4681x over previous
#include <cuda_runtime.h>
#include <cuda_fp16.h>
#include <cstdint>

#define B_ 8192
#define C_ 64
#define K_ 256
#define D_ 64
#define BTILE 64
#define NTILES 8192
#define NBLK 296
#define MARGIN 2e-3f

// ---------------- scratch (static __device__) ----------------
__device__ float g_val[B_ * C_];
__device__ int   g_idx[B_ * C_];
__device__ float g_sum[C_];
__device__ float g_sumsq[C_];
__device__ unsigned char g_flag[B_ * C_];

__device__ __forceinline__ unsigned fkey(float f) {
    unsigned u = __float_as_uint(f);
    return (u & 0x80000000u) ? ~u : (u | 0x80000000u);
}
__device__ __forceinline__ float fkey_inv(unsigned key) {
    unsigned u = (key & 0x80000000u) ? (key ^ 0x80000000u) : ~key;
    return __uint_as_float(u);
}
__device__ __forceinline__ uint32_t smem_u32(const void* p) {
    uint32_t a;
    asm("{ .reg .u64 t; cvta.to.shared.u64 t, %1; cvt.u32.u64 %0, t; }" : "=r"(a) : "l"(p));
    return a;
}

#define LDSM_X4(r0, r1, r2, r3, addr) \
    asm volatile("ldmatrix.sync.aligned.m8n8.x4.shared.b16 {%0,%1,%2,%3}, [%4];" \
        : "=r"(r0), "=r"(r1), "=r"(r2), "=r"(r3) : "r"(addr))
#define MMA_F16(c, a, b0, b1) \
    asm volatile("mma.sync.aligned.m16n8k16.row.col.f32.f16.f16.f32 " \
        "{%0,%1,%2,%3}, {%4,%5,%6,%7}, {%8,%9}, {%0,%1,%2,%3};" \
        : "+f"((c)[0]), "+f"((c)[1]), "+f"((c)[2]), "+f"((c)[3]) \
        : "r"((a)[0]), "r"((a)[1]), "r"((a)[2]), "r"((a)[3]), "r"(b0), "r"(b1))

// ---------------- smem layout (bytes) ----------------
#define SM_REDQ1 0                       // u64[2][64]
#define SM_REDQ2 1024                    // u64[2][64]
#define SM_WSUM  2048                    // f32[16]
#define SM_A     4096                    // 8192 (64x64 fp16)
#define SM_B     (4096 + 8192)           // 32768 (256x64 fp16)
#define SM_TOTAL (4096 + 8192 + 32768)   // 45056

#define RESCORE_SMEM (D_ * K_ * 4)       // 65536

__global__ void init_kernel() {
    int t = threadIdx.x;
    if (t < C_) { g_sum[t] = 0.f; g_sumsq[t] = 0.f; }
}

__device__ __forceinline__ uint32_t sw_off(int row, int cbyte) {
    return (uint32_t)(row * 128 + (cbyte ^ ((row & 7) << 4)));
}

// merge two (top1, top2) sets, each with q1 >= q2
__device__ __forceinline__ void top2_merge(unsigned long long& q1, unsigned long long& q2,
                                           unsigned long long o1, unsigned long long o2) {
    unsigned long long n1 = (q1 > o1) ? q1 : o1;
    unsigned long long lo = (q1 > o1) ? o1 : q1;
    unsigned long long hi2 = (q2 > o2) ? q2 : o2;
    q1 = n1;
    q2 = (lo > hi2) ? lo : hi2;
}

__global__ void __launch_bounds__(256, 2)
score_kernel(const float* __restrict__ inp, const float* __restrict__ cent,
             const float* __restrict__ gamma) {
    extern __shared__ char smem[];
    const int tid  = threadIdx.x;
    const int lane = tid & 31;
    const int wid  = tid >> 5;
    const int warpM = wid & 3;        // rows 16*warpM .. +15
    const int warpN = wid >> 2;       // cols 128*warpN .. +127

    const uint32_t smem_base = smem_u32(smem);
    const uint32_t sA = smem_base + SM_A;
    const uint32_t sB = smem_base + SM_B;

    const int arow = warpM * 16 + (lane & 15);
    const uint32_t aoff0 = (uint32_t)(arow * 128);
    const uint32_t aswz = (uint32_t)((arow & 7) << 4);
    const int brow = warpN * 128 + (lane & 15);
    const uint32_t boff0 = (uint32_t)(brow * 128);
    const uint32_t bswz = (uint32_t)((brow & 7) << 4);
    const uint32_t lane16 = (uint32_t)(lane & 16);

    const int T0 = (blockIdx.x * NTILES) / NBLK;
    const int T1 = ((blockIdx.x + 1) * NTILES) / NBLK;

    int cur_c = -1;
    bool useMax = true;

    for (int T = T0; T < T1; T++) {
        const int c  = T >> 7;
        const int b0 = (T & 127) * BTILE;

        // ---- (re)fill B on channel change: fp16 hi part only ----
        if (c != cur_c) {
            __syncthreads();
            cur_c = c;
            useMax = (gamma[c] >= 0.f);
            const float* Bb = cent + (size_t)c * (K_ * D_);
            for (int t = tid; t < K_ * 16; t += 256) {
                int r = t >> 4;
                int d = (t & 15) << 2;
                float4 v = *(const float4*)(Bb + (size_t)r * D_ + d);
                uint16_t h0 = __half_as_ushort(__float2half_rn(v.x));
                uint16_t h1 = __half_as_ushort(__float2half_rn(v.y));
                uint16_t h2 = __half_as_ushort(__float2half_rn(v.z));
                uint16_t h3 = __half_as_ushort(__float2half_rn(v.w));
                *(uint64_t*)(smem + SM_B + sw_off(r, d * 2)) =
                    (uint64_t)h0 | ((uint64_t)h1 << 16) | ((uint64_t)h2 << 32) | ((uint64_t)h3 << 48);
            }
        }

        // ---- fill A tile (64 rows, fp16 hi only) ----
        {
            const float* Ab = inp + (size_t)b0 * (C_ * D_) + (size_t)c * D_;
            for (int t = tid; t < BTILE * 16; t += 256) {
                int r = t >> 4;
                int d = (t & 15) << 2;
                float4 v = *(const float4*)(Ab + (size_t)r * (C_ * D_) + d);
                uint16_t h0 = __half_as_ushort(__float2half_rn(v.x));
                uint16_t h1 = __half_as_ushort(__float2half_rn(v.y));
                uint16_t h2 = __half_as_ushort(__float2half_rn(v.z));
                uint16_t h3 = __half_as_ushort(__float2half_rn(v.w));
                *(uint64_t*)(smem + SM_A + sw_off(r, d * 2)) =
                    (uint64_t)h0 | ((uint64_t)h1 << 16) | ((uint64_t)h2 << 32) | ((uint64_t)h3 << 48);
            }
        }
        __syncthreads();

        // ---- preload A fragments ----
        uint32_t ah[4][4];
        uint32_t bko[4];
#pragma unroll
        for (int ks = 0; ks < 4; ks++) {
            uint32_t kcb = (uint32_t)(ks * 32) + lane16;
            uint32_t addr = sA + aoff0 + (kcb ^ aswz);
            LDSM_X4(ah[ks][0], ah[ks][1], ah[ks][2], ah[ks][3], addr);
            bko[ks] = kcb ^ bswz;
        }
        const uint32_t bbase = sB + boff0;

        // ---- single hh MMA pass ----
        float acc[16][4];
#pragma unroll
        for (int j = 0; j < 16; j++)
#pragma unroll
            for (int e = 0; e < 4; e++) acc[j][e] = 0.f;

#pragma unroll
        for (int ks = 0; ks < 4; ks++) {
#pragma unroll
            for (int p = 0; p < 8; p++) {
                uint32_t b0r, b1r, b2r, b3r;
                LDSM_X4(b0r, b1r, b2r, b3r, bbase + (uint32_t)(p * 2048) + bko[ks]);
                MMA_F16(acc[2 * p],     ah[ks], b0r, b2r);
                MMA_F16(acc[2 * p + 1], ah[ks], b1r, b3r);
            }
        }

        // ---- epilogue: top-2 per row + sums ----
        unsigned long long q1[2] = {0ull, 0ull}, q2[2] = {0ull, 0ull};
        float s = 0.f, s2 = 0.f;
#pragma unroll
        for (int j = 0; j < 16; j++) {
#pragma unroll
            for (int e = 0; e < 4; e++) {
                float v = acc[j][e];
                s += v;
                s2 = fmaf(v, v, s2);
                int k = warpN * 128 + j * 8 + 2 * (lane & 3) + (e & 1);
                unsigned key = fkey(v);
                if (!useMax) key = ~key;
                unsigned long long p = ((unsigned long long)key << 32) | (unsigned)(255 - k);
                int r = (e >> 1);
                if (p > q1[r]) { q2[r] = q1[r]; q1[r] = p; }
                else if (p > q2[r]) q2[r] = p;
            }
        }
#pragma unroll
        for (int sh = 1; sh <= 2; sh <<= 1) {
#pragma unroll
            for (int r = 0; r < 2; r++) {
                unsigned long long o1 = __shfl_xor_sync(0xffffffffu, q1[r], sh);
                unsigned long long o2 = __shfl_xor_sync(0xffffffffu, q2[r], sh);
                top2_merge(q1[r], q2[r], o1, o2);
            }
        }
        unsigned long long* rq1 = (unsigned long long*)(smem + SM_REDQ1);  // [2][64]
        unsigned long long* rq2 = (unsigned long long*)(smem + SM_REDQ2);
        if ((lane & 3) == 0) {
            int rl = warpM * 16 + (lane >> 2);
            rq1[warpN * 64 + rl] = q1[0];
            rq2[warpN * 64 + rl] = q2[0];
            rq1[warpN * 64 + rl + 8] = q1[1];
            rq2[warpN * 64 + rl + 8] = q2[1];
        }
#pragma unroll
        for (int sh = 16; sh > 0; sh >>= 1) {
            s  += __shfl_xor_sync(0xffffffffu, s,  sh);
            s2 += __shfl_xor_sync(0xffffffffu, s2, sh);
        }
        float* wsum = (float*)(smem + SM_WSUM);
        if (lane == 0) { wsum[wid] = s; wsum[8 + wid] = s2; }
        __syncthreads();

        if (tid < BTILE) {
            unsigned long long a1 = rq1[tid], a2 = rq2[tid];
            unsigned long long b1 = rq1[64 + tid], b2 = rq2[64 + tid];
            top2_merge(a1, a2, b1, b2);
            unsigned key1 = (unsigned)(a1 >> 32);
            unsigned key2 = (unsigned)(a2 >> 32);
            float v1 = fkey_inv(useMax ? key1 : ~key1);
            float v2 = fkey_inv(useMax ? key2 : ~key2);
            int rowid = (b0 + tid) * C_ + c;
            g_val[rowid] = v1;
            g_idx[rowid] = 255 - (int)(a1 & 0xFFu);
            g_flag[rowid] = (fabsf(v1 - v2) < MARGIN) ? 1 : 0;
        }
        if (tid == 0) {
            float t1 = 0.f, t2 = 0.f;
#pragma unroll
            for (int w = 0; w < 8; w++) { t1 += wsum[w]; t2 += wsum[8 + w]; }
            atomicAdd(&g_sum[c], t1);
            atomicAdd(&g_sumsq[c], t2);
        }
        __syncthreads();
    }
}

// ---------------- exact fp32 rescore: one block per channel, codebook in smem ----------------
__global__ void __launch_bounds__(256, 1)
rescore_kernel(const float* __restrict__ inp, const float* __restrict__ cent,
               const float* __restrict__ gamma) {
    extern __shared__ float Bs[];     // [d][k] transposed, 64KB
    const int c = blockIdx.x;
    const int tid = threadIdx.x;
    const int lane = tid & 31;
    const int wid = tid >> 5;

    // stage centroids[c] transposed: Bs[d*256 + k]
    {
        const float4* Bb = (const float4*)(cent + (size_t)c * (K_ * D_));
        for (int t = tid; t < (K_ * D_) / 4; t += 256) {
            int k = t >> 4;
            int d = (t & 15) << 2;
            float4 v = Bb[t];
            Bs[(d + 0) * K_ + k] = v.x;
            Bs[(d + 1) * K_ + k] = v.y;
            Bs[(d + 2) * K_ + k] = v.z;
            Bs[(d + 3) * K_ + k] = v.w;
        }
    }
    __syncthreads();
    const bool useMax = (gamma[c] >= 0.f);

    // each warp scans 32 rows of this channel per sweep
    for (int bbase = wid * 32; bbase < B_; bbase += 8 * 32) {
        unsigned f = (unsigned)g_flag[(size_t)(bbase + lane) * C_ + c];
        unsigned mask = __ballot_sync(0xffffffffu, f != 0u);
        while (mask) {
            int bit = __ffs(mask) - 1;
            mask &= mask - 1;
            int b = bbase + bit;

            // broadcast-load x row (uniform addresses across lanes)
            const float4* x4 = (const float4*)(inp + (size_t)b * (C_ * D_) + (size_t)c * D_);
            float4 xr[16];
#pragma unroll
            for (int d = 0; d < 16; d++) xr[d] = __ldg(&x4[d]);

            unsigned long long best = 0ull;
#pragma unroll
            for (int ki = 0; ki < 8; ki++) {
                int k = ki * 32 + lane;
                float dot = 0.f;
#pragma unroll
                for (int d = 0; d < 16; d++) {
                    dot = fmaf(xr[d].x, Bs[(4 * d + 0) * K_ + k], dot);
                    dot = fmaf(xr[d].y, Bs[(4 * d + 1) * K_ + k], dot);
                    dot = fmaf(xr[d].z, Bs[(4 * d + 2) * K_ + k], dot);
                    dot = fmaf(xr[d].w, Bs[(4 * d + 3) * K_ + k], dot);
                }
                unsigned key = fkey(dot);
                if (!useMax) key = ~key;
                unsigned long long p = ((unsigned long long)key << 32) | (unsigned)(255 - k);
                best = (p > best) ? p : best;
            }
#pragma unroll
            for (int sh = 16; sh > 0; sh >>= 1) {
                unsigned long long o = __shfl_xor_sync(0xffffffffu, best, sh);
                best = (o > best) ? o : best;
            }
            if (lane == 0) {
                unsigned key = (unsigned)(best >> 32);
                int rowid = b * C_ + c;
                g_val[rowid] = fkey_inv(useMax ? key : ~key);
                g_idx[rowid] = 255 - (int)(best & 0xFFu);
            }
            __syncwarp();
        }
    }
}

// ---------------- finalize: BN affine + emit ----------------
__global__ void finalize_kernel(const float* __restrict__ gamma,
                                const float* __restrict__ beta,
                                float* __restrict__ out_codes,
                                float* __restrict__ out_mse) {
    int tid = blockIdx.x * 256 + threadIdx.x;
    if (tid >= B_ * C_) return;
    int c = tid & (C_ - 1);
    const float Ninv = 1.f / ((float)B_ * (float)K_);
    float mean = g_sum[c] * Ninv;
    float var  = fmaf(-mean, mean, g_sumsq[c] * Ninv);
    float scale = gamma[c] * rsqrtf(var + 1e-5f);
    float shift = fmaf(-mean, scale, beta[c]);
    out_codes[tid] = (float)g_idx[tid];
    out_mse[tid]   = fmaf(g_val[tid], scale, shift);
}

__global__ void copy_kernel(const float4* __restrict__ src,
                            float4* __restrict__ dst, int n4) {
    int i = blockIdx.x * blockDim.x + threadIdx.x;
    if (i < n4) dst[i] = src[i];
}

extern "C" void kernel_launch(void* const* d_in, const int* in_sizes, int n_in,
                              void* d_out, int out_size) {
    const float* inp   = (const float*)d_in[0];
    const float* cent  = (const float*)d_in[1];
    const float* gamma = (const float*)d_in[2];
    const float* beta  = (const float*)d_in[3];
    float* out = (float*)d_out;

    cudaFuncSetAttribute(score_kernel,
                         cudaFuncAttributeMaxDynamicSharedMemorySize, SM_TOTAL);
    cudaFuncSetAttribute(rescore_kernel,
                         cudaFuncAttributeMaxDynamicSharedMemorySize, RESCORE_SMEM);

    init_kernel<<<1, 64>>>();

    score_kernel<<<NBLK, 256, SM_TOTAL>>>(inp, cent, gamma);

    rescore_kernel<<<C_, 256, RESCORE_SMEM>>>(inp, cent, gamma);

    finalize_kernel<<<(B_ * C_ + 255) / 256, 256>>>(gamma, beta,
                                                    out, out + B_ * C_);

    if (out_size >= 2 * B_ * C_ + C_ * K_ * D_) {
        int n4 = (C_ * K_ * D_) / 4;
        copy_kernel<<<(n4 + 255) / 256, 256>>>((const float4*)cent,
                                               (float4*)(out + 2 * B_ * C_), n4);
    }
}